// round 1
// baseline (speedup 1.0000x reference)
#include <cuda_runtime.h>
#include <cstdint>

#define N_B 8
#define NQ  1024
#define NK  1024
#define DD  1024
#define HH  16
#define DH  64

// Scratch (device globals: allocation-free per harness rules)
__device__ float g_q[HH*N_B*NQ*DH];   // [h][n][iq][e]
__device__ float g_k[HH*N_B*NK*DH];
__device__ float g_v[HH*N_B*NK*DH];
__device__ float g_o[N_B*NQ*DD];      // [n][iq][h*64+e]

__device__ __forceinline__ uint32_t f2tf(float x) {
    uint32_t u; asm("cvt.rna.tf32.f32 %0, %1;" : "=r"(u) : "f"(x)); return u;
}

__device__ __forceinline__ void mma8(float* c, const uint32_t* a, const uint32_t* b) {
    asm volatile(
        "mma.sync.aligned.m16n8k8.row.col.f32.tf32.tf32.f32 "
        "{%0,%1,%2,%3}, {%4,%5,%6,%7}, {%8,%9}, {%0,%1,%2,%3};"
        : "+f"(c[0]), "+f"(c[1]), "+f"(c[2]), "+f"(c[3])
        : "r"(a[0]), "r"(a[1]), "r"(a[2]), "r"(a[3]), "r"(b[0]), "r"(b[1]));
}

// ---------------------------------------------------------------------------
// GEMM: C[m, r] = sum_d A[m,d] * W[r,d]   (M=8192, N=1024, K=1024, tf32 mma)
// mode 0: store to head-major layout  out[((r>>6)*8 + (m>>10))*65536 + (m&1023)*64 + (r&63)]
// mode 1: store row-major             out[m*1024 + r]
// ---------------------------------------------------------------------------
#define GPAD 20

__global__ __launch_bounds__(256) void gemm_nt(
    const float* __restrict__ A, const float* __restrict__ W,
    float* __restrict__ out, int mode)
{
    __shared__ float As[128 * GPAD];
    __shared__ float Bs[128 * GPAD];
    const int tid  = threadIdx.x;
    const int lane = tid & 31, warp = tid >> 5;
    const int wm = warp >> 2, wn = warp & 3;
    const int m0 = blockIdx.y * 128, n0 = blockIdx.x * 128;

    float c[4][4][4];
#pragma unroll
    for (int a = 0; a < 4; a++)
#pragma unroll
        for (int b = 0; b < 4; b++)
#pragma unroll
            for (int i = 0; i < 4; i++) c[a][b][i] = 0.f;

    for (int k0 = 0; k0 < DD; k0 += 16) {
#pragma unroll
        for (int i = 0; i < 2; i++) {
            int f = tid * 2 + i;           // 0..511
            int row = f >> 2, cb = (f & 3) * 4;
            float4 va = *(const float4*)(A + (size_t)(m0 + row) * DD + k0 + cb);
            As[row * GPAD + cb + 0] = __uint_as_float(f2tf(va.x));
            As[row * GPAD + cb + 1] = __uint_as_float(f2tf(va.y));
            As[row * GPAD + cb + 2] = __uint_as_float(f2tf(va.z));
            As[row * GPAD + cb + 3] = __uint_as_float(f2tf(va.w));
            float4 vb = *(const float4*)(W + (size_t)(n0 + row) * DD + k0 + cb);
            Bs[row * GPAD + cb + 0] = __uint_as_float(f2tf(vb.x));
            Bs[row * GPAD + cb + 1] = __uint_as_float(f2tf(vb.y));
            Bs[row * GPAD + cb + 2] = __uint_as_float(f2tf(vb.z));
            Bs[row * GPAD + cb + 3] = __uint_as_float(f2tf(vb.w));
        }
        __syncthreads();
#pragma unroll
        for (int kk = 0; kk < 2; kk++) {
            uint32_t af[4][4], bf[4][2];
#pragma unroll
            for (int mt = 0; mt < 4; mt++) {
                int ar = wm * 64 + mt * 16 + (lane >> 2);
                int ac = kk * 8 + (lane & 3);
                af[mt][0] = __float_as_uint(As[ar * GPAD + ac]);
                af[mt][1] = __float_as_uint(As[(ar + 8) * GPAD + ac]);
                af[mt][2] = __float_as_uint(As[ar * GPAD + ac + 4]);
                af[mt][3] = __float_as_uint(As[(ar + 8) * GPAD + ac + 4]);
            }
#pragma unroll
            for (int nt = 0; nt < 4; nt++) {
                int br = wn * 32 + nt * 8 + (lane >> 2);
                int bc = kk * 8 + (lane & 3);
                bf[nt][0] = __float_as_uint(Bs[br * GPAD + bc]);
                bf[nt][1] = __float_as_uint(Bs[br * GPAD + bc + 4]);
            }
#pragma unroll
            for (int mt = 0; mt < 4; mt++)
#pragma unroll
                for (int nt = 0; nt < 4; nt++)
                    mma8(c[mt][nt], af[mt], bf[nt]);
        }
        __syncthreads();
    }

    // store
#pragma unroll
    for (int mt = 0; mt < 4; mt++) {
        int mr = m0 + wm * 64 + mt * 16 + (lane >> 2);
#pragma unroll
        for (int nt = 0; nt < 4; nt++) {
            int nc = n0 + wn * 32 + nt * 8 + 2 * (lane & 3);
#pragma unroll
            for (int half = 0; half < 2; half++) {
                int m = mr + half * 8;
#pragma unroll
                for (int cc = 0; cc < 2; cc++) {
                    int r = nc + cc;
                    float v = c[mt][nt][half * 2 + cc];
                    if (mode == 0) {
                        size_t idx = ((size_t)((r >> 6) * N_B + (m >> 10)) << 16)
                                   + (size_t)((m & 1023) * 64 + (r & 63));
                        out[idx] = v;
                    } else {
                        out[(size_t)m * DD + r] = v;
                    }
                }
            }
        }
    }
}

// ---------------------------------------------------------------------------
// Flash-style attention with masked renormalization.
// One block = 64 q-rows of one (h,n). 4 warps, warp handles 16 rows.
// Online stats per row: m (max), Z = sum exp, S = sum exp*mask.
// Final: out = (sum exp*mask*v) / (S + EPS*Z)   == softmax*mask renormalized.
// ---------------------------------------------------------------------------
#define APAD 66
#define ATTN_SMEM (3 * 64 * APAD * (int)sizeof(float))

__global__ __launch_bounds__(128) void attn(
    const float* __restrict__ gq, const float* __restrict__ gk,
    const float* __restrict__ gv, const float* __restrict__ mask,
    float* __restrict__ go)
{
    extern __shared__ float smem[];
    float* Ks = smem;
    float* Vs = smem + 64 * APAD;
    float* Ps = smem + 2 * 64 * APAD;

    const int tid  = threadIdx.x;
    const int lane = tid & 31, warp = tid >> 5;
    const int bh = blockIdx.y;          // h*8 + n
    const int q0 = blockIdx.x * 64;
    const size_t hb = (size_t)bh * (NQ * DH);

    // Stage Q tile through Ps, pick up A-fragments into registers.
    for (int i = tid; i < 64 * 16; i += 128) {
        int row = i >> 4, cb = (i & 15) * 4;
        float4 v = *(const float4*)(gq + hb + (size_t)(q0 + row) * DH + cb);
        Ps[row * APAD + cb + 0] = __uint_as_float(f2tf(v.x));
        Ps[row * APAD + cb + 1] = __uint_as_float(f2tf(v.y));
        Ps[row * APAD + cb + 2] = __uint_as_float(f2tf(v.z));
        Ps[row * APAD + cb + 3] = __uint_as_float(f2tf(v.w));
    }
    __syncthreads();

    const int qr = warp * 16 + (lane >> 2);   // tile-local row for frag rows qr, qr+8
    uint32_t qa[8][4];
#pragma unroll
    for (int kk = 0; kk < 8; kk++) {
        int ac = kk * 8 + (lane & 3);
        qa[kk][0] = __float_as_uint(Ps[qr * APAD + ac]);
        qa[kk][1] = __float_as_uint(Ps[(qr + 8) * APAD + ac]);
        qa[kk][2] = __float_as_uint(Ps[qr * APAD + ac + 4]);
        qa[kk][3] = __float_as_uint(Ps[(qr + 8) * APAD + ac + 4]);
    }

    float o[8][4];
#pragma unroll
    for (int et = 0; et < 8; et++)
#pragma unroll
        for (int i = 0; i < 4; i++) o[et][i] = 0.f;

    float mst0 = -1e30f, mst1 = -1e30f;
    float Z0 = 0.f, Z1 = 0.f, S0 = 0.f, S1 = 0.f;

    const float* mbase = mask + (size_t)bh * ((size_t)NQ * NK)
                              + (size_t)(q0 + warp * 16 + (lane >> 2)) * NK;

    for (int kt = 0; kt < 16; kt++) {
        const int k0 = kt * 64;
        __syncthreads();   // all warps done reading Ks/Vs of previous tile
        for (int i = tid; i < 64 * 16; i += 128) {
            int row = i >> 4, cb = (i & 15) * 4;
            float4 vk = *(const float4*)(gk + hb + (size_t)(k0 + row) * DH + cb);
            Ks[row * APAD + cb + 0] = __uint_as_float(f2tf(vk.x));
            Ks[row * APAD + cb + 1] = __uint_as_float(f2tf(vk.y));
            Ks[row * APAD + cb + 2] = __uint_as_float(f2tf(vk.z));
            Ks[row * APAD + cb + 3] = __uint_as_float(f2tf(vk.w));
            float4 vv = *(const float4*)(gv + hb + (size_t)(k0 + row) * DH + cb);
            Vs[row * APAD + cb + 0] = __uint_as_float(f2tf(vv.x));
            Vs[row * APAD + cb + 1] = __uint_as_float(f2tf(vv.y));
            Vs[row * APAD + cb + 2] = __uint_as_float(f2tf(vv.z));
            Vs[row * APAD + cb + 3] = __uint_as_float(f2tf(vv.w));
        }
        __syncthreads();

        // S = Q K^T / 8   (16 q-rows x 64 keys per warp)
        float s[8][4];
#pragma unroll
        for (int nt = 0; nt < 8; nt++)
#pragma unroll
            for (int i = 0; i < 4; i++) s[nt][i] = 0.f;
#pragma unroll
        for (int kk = 0; kk < 8; kk++) {
#pragma unroll
            for (int nt = 0; nt < 8; nt++) {
                uint32_t bf[2];
                int kr = nt * 8 + (lane >> 2);
                int kc = kk * 8 + (lane & 3);
                bf[0] = __float_as_uint(Ks[kr * APAD + kc]);
                bf[1] = __float_as_uint(Ks[kr * APAD + kc + 4]);
                mma8(s[nt], qa[kk], bf);
            }
        }

        float mx0 = -1e30f, mx1 = -1e30f;
#pragma unroll
        for (int nt = 0; nt < 8; nt++) {
            s[nt][0] *= 0.125f; s[nt][1] *= 0.125f;
            s[nt][2] *= 0.125f; s[nt][3] *= 0.125f;
            mx0 = fmaxf(mx0, fmaxf(s[nt][0], s[nt][1]));
            mx1 = fmaxf(mx1, fmaxf(s[nt][2], s[nt][3]));
        }
        mx0 = fmaxf(mx0, __shfl_xor_sync(0xffffffffu, mx0, 1));
        mx0 = fmaxf(mx0, __shfl_xor_sync(0xffffffffu, mx0, 2));
        mx1 = fmaxf(mx1, __shfl_xor_sync(0xffffffffu, mx1, 1));
        mx1 = fmaxf(mx1, __shfl_xor_sync(0xffffffffu, mx1, 2));

        float nm0 = fmaxf(mst0, mx0), nm1 = fmaxf(mst1, mx1);
        float al0 = __expf(mst0 - nm0), al1 = __expf(mst1 - nm1);

        const float* mr0 = mbase + k0;
        const float* mr1 = mr0 + 8 * NK;
        float z0 = 0.f, z1 = 0.f, sm0 = 0.f, sm1 = 0.f;
#pragma unroll
        for (int nt = 0; nt < 8; nt++) {
            int cc = nt * 8 + 2 * (lane & 3);
            float p00 = __expf(s[nt][0] - nm0), p01 = __expf(s[nt][1] - nm0);
            float p10 = __expf(s[nt][2] - nm1), p11 = __expf(s[nt][3] - nm1);
            z0 += p00 + p01; z1 += p10 + p11;
            float pm00 = p00 * mr0[cc],     pm01 = p01 * mr0[cc + 1];
            float pm10 = p10 * mr1[cc],     pm11 = p11 * mr1[cc + 1];
            sm0 += pm00 + pm01; sm1 += pm10 + pm11;
            Ps[qr * APAD + cc]           = __uint_as_float(f2tf(pm00));
            Ps[qr * APAD + cc + 1]       = __uint_as_float(f2tf(pm01));
            Ps[(qr + 8) * APAD + cc]     = __uint_as_float(f2tf(pm10));
            Ps[(qr + 8) * APAD + cc + 1] = __uint_as_float(f2tf(pm11));
        }
        z0 += __shfl_xor_sync(0xffffffffu, z0, 1);  z0 += __shfl_xor_sync(0xffffffffu, z0, 2);
        z1 += __shfl_xor_sync(0xffffffffu, z1, 1);  z1 += __shfl_xor_sync(0xffffffffu, z1, 2);
        sm0 += __shfl_xor_sync(0xffffffffu, sm0, 1); sm0 += __shfl_xor_sync(0xffffffffu, sm0, 2);
        sm1 += __shfl_xor_sync(0xffffffffu, sm1, 1); sm1 += __shfl_xor_sync(0xffffffffu, sm1, 2);

        Z0 = Z0 * al0 + z0;  Z1 = Z1 * al1 + z1;
        S0 = S0 * al0 + sm0; S1 = S1 * al1 + sm1;
        mst0 = nm0; mst1 = nm1;
#pragma unroll
        for (int et = 0; et < 8; et++) {
            o[et][0] *= al0; o[et][1] *= al0;
            o[et][2] *= al1; o[et][3] *= al1;
        }
        __syncwarp();

        // O += P V   (P: 16 x 64 keys, V: 64 keys x 64 e-dims)
#pragma unroll
        for (int kk = 0; kk < 8; kk++) {
            uint32_t pa[4];
            int pc = kk * 8 + (lane & 3);
            pa[0] = __float_as_uint(Ps[qr * APAD + pc]);
            pa[1] = __float_as_uint(Ps[(qr + 8) * APAD + pc]);
            pa[2] = __float_as_uint(Ps[qr * APAD + pc + 4]);
            pa[3] = __float_as_uint(Ps[(qr + 8) * APAD + pc + 4]);
#pragma unroll
            for (int et = 0; et < 8; et++) {
                uint32_t bf[2];
                bf[0] = __float_as_uint(Vs[(kk * 8 + (lane & 3)) * APAD + et * 8 + (lane >> 2)]);
                bf[1] = __float_as_uint(Vs[(kk * 8 + (lane & 3) + 4) * APAD + et * 8 + (lane >> 2)]);
                mma8(o[et], pa, bf);
            }
        }
    }

    float d0 = 1.f / (S0 + 1e-6f * Z0);
    float d1 = 1.f / (S1 + 1e-6f * Z1);

    const int n = bh & 7, h = bh >> 3;
    float* or0 = go + (size_t)(n * NQ + q0 + warp * 16 + (lane >> 2)) * DD + h * DH;
    float* or1 = or0 + 8 * DD;
#pragma unroll
    for (int et = 0; et < 8; et++) {
        int cc = et * 8 + 2 * (lane & 3);
        or0[cc]     = o[et][0] * d0;
        or0[cc + 1] = o[et][1] * d0;
        or1[cc]     = o[et][2] * d1;
        or1[cc + 1] = o[et][3] * d1;
    }
}

// ---------------------------------------------------------------------------
extern "C" void kernel_launch(void* const* d_in, const int* in_sizes, int n_in,
                              void* d_out, int out_size)
{
    const float* q    = (const float*)d_in[0];
    const float* k    = (const float*)d_in[1];
    const float* v    = (const float*)d_in[2];
    const float* mask = (const float*)d_in[3];
    const float* Wq   = (const float*)d_in[4];
    const float* Wk   = (const float*)d_in[5];
    const float* Wv   = (const float*)d_in[6];
    const float* Wo   = (const float*)d_in[7];
    float* out = (float*)d_out;

    float *pq, *pk, *pv, *po;
    cudaGetSymbolAddress((void**)&pq, g_q);
    cudaGetSymbolAddress((void**)&pk, g_k);
    cudaGetSymbolAddress((void**)&pv, g_v);
    cudaGetSymbolAddress((void**)&po, g_o);

    cudaFuncSetAttribute(attn, cudaFuncAttributeMaxDynamicSharedMemorySize, ATTN_SMEM);

    dim3 gg(8, 64);   // N=1024/128, M=8192/128
    gemm_nt<<<gg, 256>>>(q, Wq, pq, 0);
    gemm_nt<<<gg, 256>>>(k, Wk, pk, 0);
    gemm_nt<<<gg, 256>>>(v, Wv, pv, 0);
    attn<<<dim3(16, 128), 128, ATTN_SMEM>>>(pq, pk, pv, mask, po);
    gemm_nt<<<gg, 256>>>(po, Wo, out, 1);
}